// round 14
// baseline (speedup 1.0000x reference)
#include <cuda_runtime.h>

// Maxwell RNN: per-row linear recurrence. One warp = one row, 4 warps per
// block (grid=1024: finer CTA granularity -> better per-SM balance and
// de-phased load bursts), 32 chunks of 256 elements (8/lane), one-chunk
// register prefetch. Zero smem, zero __syncthreads; warps free-run.
// Stores use evict-first streaming hint (output is write-once) to keep
// the store stream from displacing read sectors in L2.
//
//   gamma_t = (1 - 0.5*dt)*gamma_{t-1} + 0.5*dt*eps_t,  gamma_{-1} = 0
//   sig_t   = 2.5*eps_t - gamma_{t-1}
// Per chunk, sig is affine in the chunk-start state: sig_j = C_j - Pp_j*g
// (C/Pp overwrite ee/dd in place). Carry: carry = P31*carry + Q31.

constexpr int Bn    = 4096;
constexpr int Tn    = 8192;
constexpr int TPB   = 128;
constexpr int WPB   = TPB / 32;        // 4 warps = 4 rows per block
constexpr int CHUNK = 256;             // elements per warp-chunk
constexpr int EPT   = 8;               // elements per lane per chunk
constexpr int NCH   = Tn / CHUNK;      // 32 chunks per row
constexpr int GRID  = Bn / WPB;        // 1024 blocks

__global__ void __launch_bounds__(TPB)
maxwell_warp_kernel(const float* __restrict__ eps, const float* __restrict__ dt,
                    float* __restrict__ out) {
    const int lane = threadIdx.x & 31;
    const int wid  = threadIdx.x >> 5;

    // 32-bit element offset of this lane's first element (33.5M < 2^32)
    unsigned off = (blockIdx.x * WPB + wid) * (unsigned)Tn + lane * EPT;

    // ---- prefetch chunk 0 ----
    float4 ce0 = *reinterpret_cast<const float4*>(eps + off);
    float4 ce1 = *reinterpret_cast<const float4*>(eps + off + 4);
    float4 cd0 = *reinterpret_cast<const float4*>(dt  + off);
    float4 cd1 = *reinterpret_cast<const float4*>(dt  + off + 4);

    float carry = 0.0f;                 // gamma entering current chunk

    #pragma unroll 2
    for (int c = 0; c < NCH; c++) {
        // ---- prefetch next chunk while current is processed ----
        float4 ne0, ne1, nd0, nd1;
        if (c + 1 < NCH) {
            unsigned noff = off + CHUNK;
            ne0 = *reinterpret_cast<const float4*>(eps + noff);
            ne1 = *reinterpret_cast<const float4*>(eps + noff + 4);
            nd0 = *reinterpret_cast<const float4*>(dt  + noff);
            nd1 = *reinterpret_cast<const float4*>(dt  + noff + 4);
        }

        float ee[EPT] = { ce0.x, ce0.y, ce0.z, ce0.w, ce1.x, ce1.y, ce1.z, ce1.w };
        float dd[EPT] = { cd0.x, cd0.y, cd0.z, cd0.w, cd1.x, cd1.y, cd1.z, cd1.w };

        // ---- local affine fold; rewrite (ee,dd) -> (C, Pp) in place ----
        float P = 1.0f, Q = 0.0f;
        #pragma unroll
        for (int j = 0; j < EPT; j++) {
            float e = ee[j];
            float d = dd[j];
            dd[j] = P;                      // Pp_j
            ee[j] = fmaf(2.5f, e, -Q);      // C_j
            float ad = 0.5f * d;
            float A  = 1.0f - ad;
            Q = fmaf(A, Q, ad * e);
            P = P * A;
        }

        // ---- warp-inclusive affine scan (5 shuffle steps) ----
        #pragma unroll
        for (int s = 1; s < 32; s <<= 1) {
            float Pu = __shfl_up_sync(0xFFFFFFFFu, P, s);
            float Qu = __shfl_up_sync(0xFFFFFFFFu, Q, s);
            if (lane >= s) { Q = fmaf(P, Qu, Q); P *= Pu; }
        }
        // lane-exclusive prefix -> this lane's chunk-start gamma
        float LPe = __shfl_up_sync(0xFFFFFFFFu, P, 1);
        float LQe = __shfl_up_sync(0xFFFFFFFFu, Q, 1);
        if (lane == 0) { LPe = 1.0f; LQe = 0.0f; }
        float gt = fmaf(LPe, carry, LQe);

        // ---- carry gamma to next chunk (lane-31 inclusive aggregate) ----
        float P31 = __shfl_sync(0xFFFFFFFFu, P, 31);
        float Q31 = __shfl_sync(0xFFFFFFFFu, Q, 31);
        carry = fmaf(P31, carry, Q31);

        // ---- fixup (independent FMAs) + streaming coalesced stores ----
        float4 o0, o1;
        o0.x = fmaf(-dd[0], gt, ee[0]);
        o0.y = fmaf(-dd[1], gt, ee[1]);
        o0.z = fmaf(-dd[2], gt, ee[2]);
        o0.w = fmaf(-dd[3], gt, ee[3]);
        o1.x = fmaf(-dd[4], gt, ee[4]);
        o1.y = fmaf(-dd[5], gt, ee[5]);
        o1.z = fmaf(-dd[6], gt, ee[6]);
        o1.w = fmaf(-dd[7], gt, ee[7]);
        __stcs(reinterpret_cast<float4*>(out + off),     o0);
        __stcs(reinterpret_cast<float4*>(out + off + 4), o1);

        ce0 = ne0; ce1 = ne1; cd0 = nd0; cd1 = nd1;
        off += CHUNK;
    }
}

extern "C" void kernel_launch(void* const* d_in, const int* in_sizes, int n_in,
                              void* d_out, int out_size) {
    const float* eps = (const float*)d_in[0];
    const float* dt  = (const float*)d_in[1];
    float* out = (float*)d_out;

    maxwell_warp_kernel<<<GRID, TPB>>>(eps, dt, out);
}